// round 11
// baseline (speedup 1.0000x reference)
#include <cuda_runtime.h>
#include <cuda_fp16.h>
#include <math.h>

#define Nn 50000
#define Ee 1600000
#define INF_FEATS 64
#define Hh 128
#define Ll 5
#define Gg 512
#define Cc 10

#define HS 136   // half-stride per smem tile row: 128 + 8 pad -> word stride 68 ≡ 4 (mod 32)
#define WS 68    // word (uint32/half2) stride

// ---------------- scratch (device globals; no allocation allowed) ----------
__device__ float  d_h[Nn * Hh];            // node state
__device__ __half d_m16[Nn * Hh];          // m = h @ W_l, fp16 (gather source)
__device__ float  d_gh[Nn * 3 * Hh];       // h @ w_hh^T + b_hh
__device__ float  d_agg[Nn * Hh];          // gathered messages (fp32 acc)
__device__ float  d_gi[Nn * 3 * Hh];       // agg @ w_ih^T + b_ih
__device__ __half d_wih16[3 * Hh * Hh];    // w_ih [384][128] fp16 (n-major)
__device__ __half d_Bcat16[Ll * 512 * Hh]; // per-layer [c][k] fp16 (n-major B^T)
__device__ float  d_bcat[512];             // [0 | b_hh]
__device__ float  d_pooled[Gg * Hh];
__device__ float  d_hid[Gg * 4 * Hh];
// CSR scratch
__device__ int    d_deg[Nn];
__device__ int    d_rowstart[Nn + 1];
__device__ int    d_cursor[Nn];
__device__ int    d_esrc[Ee];
__device__ float  d_ews[Ee];

// ---------------- helpers ---------------------------------------------------
__device__ __forceinline__ float sigmoidf_(float x) {
    return 1.0f / (1.0f + expf(-x));
}

__device__ __forceinline__ void mma_f16(float c[4], const unsigned a[4],
                                        const unsigned b[2]) {
    asm volatile(
        "mma.sync.aligned.m16n8k16.row.col.f32.f16.f16.f32 "
        "{%0,%1,%2,%3}, {%4,%5,%6,%7}, {%8,%9}, {%0,%1,%2,%3};"
        : "+f"(c[0]), "+f"(c[1]), "+f"(c[2]), "+f"(c[3])
        : "r"(a[0]), "r"(a[1]), "r"(a[2]), "r"(a[3]), "r"(b[0]), "r"(b[1]));
}

// ---------------- setup kernels ---------------------------------------------

__global__ void k_init_h(const float* __restrict__ x) {
    int i = blockIdx.x * blockDim.x + threadIdx.x;
    if (i >= Nn * Hh) return;
    int n = i >> 7, f = i & 127;
    d_h[i] = (f < INF_FEATS) ? x[n * INF_FEATS + f] : 0.0f;
}

// wih16[n][k] = fp16(w_ih[n][k])  (identity layout copy-convert)
__global__ void k_prep_wih(const float* __restrict__ wih) {
    int i = blockIdx.x * blockDim.x + threadIdx.x;
    if (i < 3 * Hh * Hh) d_wih16[i] = __float2half_rn(wih[i]);
}

// Bcat16[l][c][k] = fp16( c<128 ? weight[l][k][c] : w_hh[c-128][k] ); bcat
__global__ void k_build_bcat(const float* __restrict__ weight,
                             const float* __restrict__ whh,
                             const float* __restrict__ bhh) {
    int i = blockIdx.x * blockDim.x + threadIdx.x;
    if (i < 512) d_bcat[i] = (i < 128) ? 0.0f : bhh[i - 128];
    if (i >= Ll * 512 * Hh) return;
    int l = i / (512 * Hh);
    int r = i % (512 * Hh);
    int c = r / Hh, k = r % Hh;
    float v = (c < 128) ? weight[(size_t)l * Hh * Hh + k * Hh + c]
                        : whh[(size_t)(c - 128) * Hh + k];
    d_Bcat16[i] = __float2half_rn(v);
}

// ---------------- CSR build --------------------------------------------------
__global__ void k_deg_zero() {
    int i = blockIdx.x * blockDim.x + threadIdx.x;
    if (i < Nn) d_deg[i] = 0;
}

__global__ void k_hist(const int* __restrict__ ei) {
    int e = blockIdx.x * blockDim.x + threadIdx.x;
    if (e < Ee) atomicAdd(&d_deg[ei[Ee + e]], 1);
}

__global__ void k_scan() {
    __shared__ int sp[1024];
    const int CH = (Nn + 1023) / 1024;
    int t = threadIdx.x;
    int base = t * CH;
    int s = 0;
    for (int i = 0; i < CH; i++) {
        int idx = base + i;
        if (idx < Nn) s += d_deg[idx];
    }
    sp[t] = s;
    __syncthreads();
    for (int d = 1; d < 1024; d <<= 1) {
        int add = (t >= d) ? sp[t - d] : 0;
        __syncthreads();
        sp[t] += add;
        __syncthreads();
    }
    int off = sp[t] - s;
    for (int i = 0; i < CH; i++) {
        int idx = base + i;
        if (idx < Nn) {
            d_rowstart[idx] = off;
            d_cursor[idx] = off;
            off += d_deg[idx];
        }
    }
    if (t == 1023) d_rowstart[Nn] = off;
}

__global__ void k_scatter(const int* __restrict__ ei, const float* __restrict__ ew) {
    int e = blockIdx.x * blockDim.x + threadIdx.x;
    if (e >= Ee) return;
    int dst = ei[Ee + e];
    int pos = atomicAdd(&d_cursor[dst], 1);
    d_esrc[pos] = ei[e];
    d_ews[pos] = ew[e];
}

// ---------------- GEMM (fp16 m16n8k16 tensor cores, 2 CTAs/SM) ---------------
// C = A[M,128] @ B16^T (+bias).  B16 n-major [Nw][128] fp16.
// If Cm != nullptr (fused layer call, Nw=512): block column n0==0 writes fp16
// m to Cm [M,128]; block columns n0>=128 write fp32 to C [M,Cstride] at
// col-128. Branch is uniform per CTA.
__global__ void __launch_bounds__(256, 2)
k_gemm_h(const float* __restrict__ A, const __half* __restrict__ B16,
         const float* __restrict__ bias, float* __restrict__ C,
         __half* __restrict__ Cm, int M, int Cstride) {
    extern __shared__ __half smh[];
    __half* Ash = smh;               // [128][HS]  (m-major, k cols)
    __half* Bsh = smh + 128 * HS;    // [128][HS]  (n-major, k cols)

    int m0 = blockIdx.x * 128;
    int n0 = blockIdx.y * 128;
    int tid = threadIdx.x;

    // A tile: 128 rows x 128 k (fp32 -> fp16)
    #pragma unroll
    for (int i = 0; i < 16; i++) {
        int e = tid + i * 256;
        int r = e >> 5, c4 = e & 31;
        float4 v = make_float4(0.f, 0.f, 0.f, 0.f);
        if (m0 + r < M)
            v = reinterpret_cast<const float4*>(A + (size_t)(m0 + r) * 128)[c4];
        __half2* dst = reinterpret_cast<__half2*>(Ash + r * HS + c4 * 4);
        dst[0] = __floats2half2_rn(v.x, v.y);
        dst[1] = __floats2half2_rn(v.z, v.w);
    }
    // B tile: 128 n-rows x 128 k (fp16 raw copy)
    #pragma unroll
    for (int i = 0; i < 8; i++) {
        int e = tid + i * 256;
        int r = e >> 4, c4 = e & 15;
        float4 v = reinterpret_cast<const float4*>(B16 + (size_t)(n0 + r) * 128)[c4];
        reinterpret_cast<float4*>(Bsh + r * HS)[c4] = v;
    }
    __syncthreads();

    int wid = tid >> 5, lane = tid & 31;
    int wm = (wid & 3) * 32;
    int wn = (wid >> 2) * 64;
    int lr = lane >> 2;
    int lc = lane & 3;

    float acc[2][8][4];
    #pragma unroll
    for (int mt = 0; mt < 2; mt++)
        #pragma unroll
        for (int nt = 0; nt < 8; nt++)
            #pragma unroll
            for (int q = 0; q < 4; q++) acc[mt][nt][q] = 0.0f;

    const unsigned* Asu = reinterpret_cast<const unsigned*>(Ash);
    const unsigned* Bsu = reinterpret_cast<const unsigned*>(Bsh);

    #pragma unroll
    for (int ks = 0; ks < 8; ks++) {
        int kh = ks * 8;
        unsigned a[2][4], b[8][2];
        #pragma unroll
        for (int mt = 0; mt < 2; mt++) {
            const unsigned* ap = Asu + (wm + mt * 16 + lr) * WS + kh + lc;
            a[mt][0] = ap[0];
            a[mt][1] = ap[8 * WS];
            a[mt][2] = ap[4];
            a[mt][3] = ap[8 * WS + 4];
        }
        #pragma unroll
        for (int nt = 0; nt < 8; nt++) {
            const unsigned* bp = Bsu + (wn + nt * 8 + lr) * WS + kh + lc;
            b[nt][0] = bp[0];
            b[nt][1] = bp[4];
        }
        #pragma unroll
        for (int mt = 0; mt < 2; mt++)
            #pragma unroll
            for (int nt = 0; nt < 8; nt++)
                mma_f16(acc[mt][nt], a[mt], b[nt]);
    }

    bool is_m = (Cm != nullptr) && (n0 == 0);   // uniform per CTA
    int coff = (Cm != nullptr) ? 128 : 0;       // gh/gi column offset

    #pragma unroll
    for (int mt = 0; mt < 2; mt++) {
        #pragma unroll
        for (int nt = 0; nt < 8; nt++) {
            int row = m0 + wm + mt * 16 + lr;
            int col = n0 + wn + nt * 8 + lc * 2;
            float b0 = bias ? bias[col] : 0.0f;
            float b1 = bias ? bias[col + 1] : 0.0f;
            if (is_m) {
                if (row < M)
                    *reinterpret_cast<__half2*>(Cm + (size_t)row * 128 + col) =
                        __floats2half2_rn(acc[mt][nt][0] + b0, acc[mt][nt][1] + b1);
                if (row + 8 < M)
                    *reinterpret_cast<__half2*>(Cm + (size_t)(row + 8) * 128 + col) =
                        __floats2half2_rn(acc[mt][nt][2] + b0, acc[mt][nt][3] + b1);
            } else {
                int cc = col - coff;
                if (row < M) {
                    float2 v = make_float2(acc[mt][nt][0] + b0, acc[mt][nt][1] + b1);
                    *reinterpret_cast<float2*>(C + (size_t)row * Cstride + cc) = v;
                }
                if (row + 8 < M) {
                    float2 v = make_float2(acc[mt][nt][2] + b0, acc[mt][nt][3] + b1);
                    *reinterpret_cast<float2*>(C + (size_t)(row + 8) * Cstride + cc) = v;
                }
            }
        }
    }
}

// ---------------- CSR aggregation: warp per node ------------------------------
// agg[n] = sum_e m16[src(e)] * w(e).  Each lane owns 4 features (8 B = uint2).
__global__ void k_agg() {
    int warp = (blockIdx.x * blockDim.x + threadIdx.x) >> 5;
    if (warp >= Nn) return;
    int lane = threadIdx.x & 31;
    int beg = d_rowstart[warp];
    int end = d_rowstart[warp + 1];
    float4 acc = make_float4(0.f, 0.f, 0.f, 0.f);
    for (int base = beg; base < end; base += 32) {
        int idx = base + lane;
        int sid = 0;
        float w = 0.0f;
        if (idx < end) { sid = d_esrc[idx]; w = d_ews[idx]; }
        int cnt = min(32, end - base);
        #pragma unroll 4
        for (int j = 0; j < cnt; j++) {
            int s = __shfl_sync(0xffffffff, sid, j);
            float wj = __shfl_sync(0xffffffff, w, j);
            uint2 u = reinterpret_cast<const uint2*>(
                          d_m16 + (size_t)s * 128)[lane];
            float2 f0 = __half22float2(*reinterpret_cast<__half2*>(&u.x));
            float2 f1 = __half22float2(*reinterpret_cast<__half2*>(&u.y));
            acc.x = fmaf(f0.x, wj, acc.x);
            acc.y = fmaf(f0.y, wj, acc.y);
            acc.z = fmaf(f1.x, wj, acc.z);
            acc.w = fmaf(f1.y, wj, acc.w);
        }
    }
    *reinterpret_cast<float4*>(d_agg + (size_t)warp * 128 + lane * 4) = acc;
}

// ---------------- GRU --------------------------------------------------------
__global__ void k_gru() {
    int n = blockIdx.x;
    int f = threadIdx.x;
    const float* gi = d_gi + (size_t)n * 384;
    const float* gh = d_gh + (size_t)n * 384;
    float r  = sigmoidf_(gi[f] + gh[f]);
    float z  = sigmoidf_(gi[128 + f] + gh[128 + f]);
    float nn = tanhf(gi[256 + f] + r * gh[256 + f]);
    float ho = d_h[(size_t)n * 128 + f];
    d_h[(size_t)n * 128 + f] = (1.0f - z) * nn + z * ho;
}

// ---------------- pooling + MLP ----------------------------------------------
__global__ void k_pool_init() {
    int i = blockIdx.x * blockDim.x + threadIdx.x;
    if (i < Gg * Hh) d_pooled[i] = -INFINITY;
}

__global__ void k_pool(const int* __restrict__ batch) {
    int i = blockIdx.x * blockDim.x + threadIdx.x;
    if (i >= Nn * Hh) return;
    int n = i >> 7, f = i & 127;
    float v = d_h[i];
    int g = batch[n];
    float* addr = &d_pooled[g * Hh + f];
    if (v >= 0.0f)
        atomicMax(reinterpret_cast<int*>(addr), __float_as_int(v));
    else
        atomicMin(reinterpret_cast<unsigned*>(addr), __float_as_uint(v));
}

__global__ void k_mlp1(const float* __restrict__ w, const float* __restrict__ b) {
    __shared__ float p[Hh];
    int g = blockIdx.x;
    p[threadIdx.x] = d_pooled[g * Hh + threadIdx.x];
    __syncthreads();
    for (int o = threadIdx.x; o < 4 * Hh; o += blockDim.x) {
        const float* wr = w + (size_t)o * Hh;
        float s = b[o];
        #pragma unroll 4
        for (int k = 0; k < Hh; k++) s = fmaf(p[k], wr[k], s);
        d_hid[g * 4 * Hh + o] = fmaxf(s, 0.0f);
    }
}

__global__ void k_mlp2(const float* __restrict__ w, const float* __restrict__ b,
                       float* __restrict__ out) {
    __shared__ float hsh[4 * Hh];
    int g = blockIdx.x;
    for (int i = threadIdx.x; i < 4 * Hh; i += blockDim.x)
        hsh[i] = d_hid[g * 4 * Hh + i];
    __syncthreads();
    int warp = threadIdx.x >> 5, lane = threadIdx.x & 31;
    if (warp < Cc) {
        const float* wr = w + (size_t)warp * (4 * Hh);
        float s = 0.0f;
        for (int k = lane; k < 4 * Hh; k += 32) s = fmaf(hsh[k], wr[k], s);
        #pragma unroll
        for (int off = 16; off; off >>= 1)
            s += __shfl_down_sync(0xffffffff, s, off);
        if (lane == 0) out[g * Cc + warp] = s + b[warp];
    }
}

// ---------------- launch ------------------------------------------------------
extern "C" void kernel_launch(void* const* d_in, const int* in_sizes, int n_in,
                              void* d_out, int out_size) {
    const float* x     = (const float*)d_in[0];
    const int*   ei    = (const int*)  d_in[1];
    const int*   batch = (const int*)  d_in[2];
    const float* ew    = (const float*)d_in[3];
    const float* weight= (const float*)d_in[4];
    const float* w_ih  = (const float*)d_in[5];
    const float* w_hh  = (const float*)d_in[6];
    const float* b_ih  = (const float*)d_in[7];
    const float* b_hh  = (const float*)d_in[8];
    const float* d1w   = (const float*)d_in[9];
    const float* d1b   = (const float*)d_in[10];
    const float* d2w   = (const float*)d_in[11];
    const float* d2b   = (const float*)d_in[12];
    float* out = (float*)d_out;

    float  *ph, *pgh, *pagg, *pgi, *pbcat;
    __half *pm16, *pwih16, *pBcat16;
    cudaGetSymbolAddress((void**)&ph,      d_h);
    cudaGetSymbolAddress((void**)&pm16,    d_m16);
    cudaGetSymbolAddress((void**)&pgh,     d_gh);
    cudaGetSymbolAddress((void**)&pagg,    d_agg);
    cudaGetSymbolAddress((void**)&pgi,     d_gi);
    cudaGetSymbolAddress((void**)&pwih16,  d_wih16);
    cudaGetSymbolAddress((void**)&pBcat16, d_Bcat16);
    cudaGetSymbolAddress((void**)&pbcat,   d_bcat);

    const int GEMM_SMEM = 2 * 128 * HS * (int)sizeof(__half);   // 69.6 KB
    cudaFuncSetAttribute(k_gemm_h, cudaFuncAttributeMaxDynamicSharedMemorySize,
                         GEMM_SMEM);

    const int NH = Nn * Hh;
    // setup
    k_init_h<<<(NH + 255) / 256, 256>>>(x);
    k_prep_wih<<<(3 * Hh * Hh + 255) / 256, 256>>>(w_ih);
    k_build_bcat<<<(Ll * 512 * Hh + 255) / 256, 256>>>(weight, w_hh, b_hh);
    // CSR build
    k_deg_zero<<<(Nn + 255) / 256, 256>>>();
    k_hist<<<(Ee + 255) / 256, 256>>>(ei);
    k_scan<<<1, 1024>>>();
    k_scatter<<<(Ee + 255) / 256, 256>>>(ei, ew);

    const int MB = (Nn + 127) / 128;  // 391 row tiles
    for (int l = 0; l < Ll; l++) {
        // [m16 | gh] = h @ [W_l | w_hh^T]  (m -> fp16, gh -> fp32)
        k_gemm_h<<<dim3(MB, 4), 256, GEMM_SMEM>>>(
            ph, pBcat16 + (size_t)l * 512 * Hh, pbcat, pgh, pm16, Nn, 384);
        // agg = CSR gather of m16[src]*w (fp32 accumulate)
        k_agg<<<(Nn * 32 + 255) / 256, 256>>>();
        // gi = agg @ w_ih^T + b_ih
        k_gemm_h<<<dim3(MB, 3), 256, GEMM_SMEM>>>(
            pagg, pwih16, b_ih, pgi, nullptr, Nn, 384);
        // h = GRU(agg, h)
        k_gru<<<Nn, Hh>>>();
    }

    k_pool_init<<<(Gg * Hh + 255) / 256, 256>>>();
    k_pool<<<(NH + 255) / 256, 256>>>(batch);
    k_mlp1<<<Gg, Hh>>>(d1w, d1b);
    k_mlp2<<<Gg, 320>>>(d2w, d2b, out);
}

// round 13
// speedup vs baseline: 1.3970x; 1.3970x over previous
#include <cuda_runtime.h>
#include <cuda_fp16.h>
#include <math.h>

#define Nn 50000
#define Ee 1600000
#define INF_FEATS 64
#define Hh 128
#define Ll 5
#define Gg 512
#define Cc 10

#define HS 136   // half-stride per smem tile row: 128 + 8 pad -> word stride 68 ≡ 4 (mod 32)
#define WS 68    // word (uint32/half2) stride

// ---------------- scratch (device globals; no allocation allowed) ----------
__device__ float  d_h[Nn * Hh];            // node state
__device__ float  d_mgh[Nn * 512];         // [m (128) | gh (384)] fused GEMM out
__device__ __half d_m16[Nn * Hh];          // fp16 copy of m (gather source)
__device__ float  d_agg[Nn * Hh];          // gathered messages
__device__ float  d_gi[Nn * 3 * Hh];       // agg @ w_ih^T
__device__ __half d_wih16[3 * Hh * Hh];    // w_ih [384][128] fp16 (n-major)
__device__ __half d_Bcat16[Ll * 512 * Hh]; // per-layer [c][k] fp16 (n-major B^T)
__device__ float  d_bcat[512];             // [0 | b_hh]
__device__ float  d_pooled[Gg * Hh];
__device__ float  d_hid[Gg * 4 * Hh];
// CSR scratch
__device__ int    d_deg[Nn];
__device__ int    d_rowstart[Nn + 1];
__device__ int    d_cursor[Nn];
__device__ int    d_esrc[Ee];
__device__ float  d_ews[Ee];

// ---------------- helpers ---------------------------------------------------
__device__ __forceinline__ float sigmoidf_(float x) {
    return 1.0f / (1.0f + expf(-x));
}

__device__ __forceinline__ void mma_f16(float c[4], const unsigned a[4],
                                        const unsigned b[2]) {
    asm volatile(
        "mma.sync.aligned.m16n8k16.row.col.f32.f16.f16.f32 "
        "{%0,%1,%2,%3}, {%4,%5,%6,%7}, {%8,%9}, {%0,%1,%2,%3};"
        : "+f"(c[0]), "+f"(c[1]), "+f"(c[2]), "+f"(c[3])
        : "r"(a[0]), "r"(a[1]), "r"(a[2]), "r"(a[3]), "r"(b[0]), "r"(b[1]));
}

// ---------------- setup kernels ---------------------------------------------

__global__ void k_init_h(const float* __restrict__ x) {
    int i = blockIdx.x * blockDim.x + threadIdx.x;
    if (i >= Nn * Hh) return;
    int n = i >> 7, f = i & 127;
    d_h[i] = (f < INF_FEATS) ? x[n * INF_FEATS + f] : 0.0f;
}

// wih16[n][k] = fp16(w_ih[n][k])  (identity layout copy-convert)
__global__ void k_prep_wih(const float* __restrict__ wih) {
    int i = blockIdx.x * blockDim.x + threadIdx.x;
    if (i < 3 * Hh * Hh) d_wih16[i] = __float2half_rn(wih[i]);
}

// Bcat16[l][c][k] = fp16( c<128 ? weight[l][k][c] : w_hh[c-128][k] ); bcat
__global__ void k_build_bcat(const float* __restrict__ weight,
                             const float* __restrict__ whh,
                             const float* __restrict__ bhh) {
    int i = blockIdx.x * blockDim.x + threadIdx.x;
    if (i < 512) d_bcat[i] = (i < 128) ? 0.0f : bhh[i - 128];
    if (i >= Ll * 512 * Hh) return;
    int l = i / (512 * Hh);
    int r = i % (512 * Hh);
    int c = r / Hh, k = r % Hh;
    float v = (c < 128) ? weight[(size_t)l * Hh * Hh + k * Hh + c]
                        : whh[(size_t)(c - 128) * Hh + k];
    d_Bcat16[i] = __float2half_rn(v);
}

// ---------------- CSR build --------------------------------------------------
__global__ void k_deg_zero() {
    int i = blockIdx.x * blockDim.x + threadIdx.x;
    if (i < Nn) d_deg[i] = 0;
}

__global__ void k_hist(const int* __restrict__ ei) {
    int e = blockIdx.x * blockDim.x + threadIdx.x;
    if (e < Ee) atomicAdd(&d_deg[ei[Ee + e]], 1);
}

__global__ void k_scan() {
    __shared__ int sp[1024];
    const int CH = (Nn + 1023) / 1024;
    int t = threadIdx.x;
    int base = t * CH;
    int s = 0;
    for (int i = 0; i < CH; i++) {
        int idx = base + i;
        if (idx < Nn) s += d_deg[idx];
    }
    sp[t] = s;
    __syncthreads();
    for (int d = 1; d < 1024; d <<= 1) {
        int add = (t >= d) ? sp[t - d] : 0;
        __syncthreads();
        sp[t] += add;
        __syncthreads();
    }
    int off = sp[t] - s;
    for (int i = 0; i < CH; i++) {
        int idx = base + i;
        if (idx < Nn) {
            d_rowstart[idx] = off;
            d_cursor[idx] = off;
            off += d_deg[idx];
        }
    }
    if (t == 1023) d_rowstart[Nn] = off;
}

__global__ void k_scatter(const int* __restrict__ ei, const float* __restrict__ ew) {
    int e = blockIdx.x * blockDim.x + threadIdx.x;
    if (e >= Ee) return;
    int dst = ei[Ee + e];
    int pos = atomicAdd(&d_cursor[dst], 1);
    d_esrc[pos] = ei[e];
    d_ews[pos] = ew[e];
}

// ---------------- GEMM (fp16 m16n8k16 tensor cores, 2 CTAs/SM) ---------------
// EXACT R10 kernel: C[M,Nw] = A[M,128] @ B16^T (+bias), B16 n-major [Nw][128].
__global__ void __launch_bounds__(256, 2)
k_gemm_h(const float* __restrict__ A, const __half* __restrict__ B16,
         const float* __restrict__ bias, float* __restrict__ C,
         int M, int Nw) {
    extern __shared__ __half smh[];
    __half* Ash = smh;               // [128][HS]  (m-major, k cols)
    __half* Bsh = smh + 128 * HS;    // [128][HS]  (n-major, k cols)

    int m0 = blockIdx.x * 128;
    int n0 = blockIdx.y * 128;
    int tid = threadIdx.x;

    #pragma unroll
    for (int i = 0; i < 16; i++) {
        int e = tid + i * 256;
        int r = e >> 5, c4 = e & 31;
        float4 v = make_float4(0.f, 0.f, 0.f, 0.f);
        if (m0 + r < M)
            v = reinterpret_cast<const float4*>(A + (size_t)(m0 + r) * 128)[c4];
        __half2* dst = reinterpret_cast<__half2*>(Ash + r * HS + c4 * 4);
        dst[0] = __floats2half2_rn(v.x, v.y);
        dst[1] = __floats2half2_rn(v.z, v.w);
    }
    #pragma unroll
    for (int i = 0; i < 8; i++) {
        int e = tid + i * 256;
        int r = e >> 4, c4 = e & 15;
        float4 v = reinterpret_cast<const float4*>(B16 + (size_t)(n0 + r) * 128)[c4];
        reinterpret_cast<float4*>(Bsh + r * HS)[c4] = v;
    }
    __syncthreads();

    int wid = tid >> 5, lane = tid & 31;
    int wm = (wid & 3) * 32;
    int wn = (wid >> 2) * 64;
    int lr = lane >> 2;
    int lc = lane & 3;

    float acc[2][8][4];
    #pragma unroll
    for (int mt = 0; mt < 2; mt++)
        #pragma unroll
        for (int nt = 0; nt < 8; nt++)
            #pragma unroll
            for (int q = 0; q < 4; q++) acc[mt][nt][q] = 0.0f;

    const unsigned* Asu = reinterpret_cast<const unsigned*>(Ash);
    const unsigned* Bsu = reinterpret_cast<const unsigned*>(Bsh);

    #pragma unroll
    for (int ks = 0; ks < 8; ks++) {
        int kh = ks * 8;
        unsigned a[2][4], b[8][2];
        #pragma unroll
        for (int mt = 0; mt < 2; mt++) {
            const unsigned* ap = Asu + (wm + mt * 16 + lr) * WS + kh + lc;
            a[mt][0] = ap[0];
            a[mt][1] = ap[8 * WS];
            a[mt][2] = ap[4];
            a[mt][3] = ap[8 * WS + 4];
        }
        #pragma unroll
        for (int nt = 0; nt < 8; nt++) {
            const unsigned* bp = Bsu + (wn + nt * 8 + lr) * WS + kh + lc;
            b[nt][0] = bp[0];
            b[nt][1] = bp[4];
        }
        #pragma unroll
        for (int mt = 0; mt < 2; mt++)
            #pragma unroll
            for (int nt = 0; nt < 8; nt++)
                mma_f16(acc[mt][nt], a[mt], b[nt]);
    }

    #pragma unroll
    for (int mt = 0; mt < 2; mt++) {
        #pragma unroll
        for (int nt = 0; nt < 8; nt++) {
            int row = m0 + wm + mt * 16 + lr;
            int col = n0 + wn + nt * 8 + lc * 2;
            float b0 = bias ? bias[col] : 0.0f;
            float b1 = bias ? bias[col + 1] : 0.0f;
            if (row < M) {
                float2 v = make_float2(acc[mt][nt][0] + b0, acc[mt][nt][1] + b1);
                *reinterpret_cast<float2*>(C + (size_t)row * Nw + col) = v;
            }
            if (row + 8 < M) {
                float2 v = make_float2(acc[mt][nt][2] + b0, acc[mt][nt][3] + b1);
                *reinterpret_cast<float2*>(C + (size_t)(row + 8) * Nw + col) = v;
            }
        }
    }
}

// ---------------- m (fp32, stride 512) -> m16 (fp16, compact) -----------------
__global__ void k_m2h() {
    int i = blockIdx.x * blockDim.x + threadIdx.x;   // half2 index
    if (i >= Nn * 64) return;
    int n = i >> 6, c2 = i & 63;
    float2 v = *reinterpret_cast<const float2*>(d_mgh + (size_t)n * 512 + c2 * 2);
    *reinterpret_cast<__half2*>(d_m16 + (size_t)n * 128 + c2 * 2) =
        __floats2half2_rn(v.x, v.y);
}

// ---------------- CSR aggregation: warp per node ------------------------------
// agg[n] = sum_e m16[src(e)] * w(e).  Lane owns 4 features (uint2 = 8 B).
__global__ void k_agg() {
    int warp = (blockIdx.x * blockDim.x + threadIdx.x) >> 5;
    if (warp >= Nn) return;
    int lane = threadIdx.x & 31;
    int beg = d_rowstart[warp];
    int end = d_rowstart[warp + 1];
    float4 acc = make_float4(0.f, 0.f, 0.f, 0.f);
    for (int base = beg; base < end; base += 32) {
        int idx = base + lane;
        int sid = 0;
        float w = 0.0f;
        if (idx < end) { sid = d_esrc[idx]; w = d_ews[idx]; }
        int cnt = min(32, end - base);
        #pragma unroll 4
        for (int j = 0; j < cnt; j++) {
            int s = __shfl_sync(0xffffffff, sid, j);
            float wj = __shfl_sync(0xffffffff, w, j);
            uint2 u = reinterpret_cast<const uint2*>(d_m16 + (size_t)s * 128)[lane];
            float2 f0 = __half22float2(*reinterpret_cast<__half2*>(&u.x));
            float2 f1 = __half22float2(*reinterpret_cast<__half2*>(&u.y));
            acc.x = fmaf(f0.x, wj, acc.x);
            acc.y = fmaf(f0.y, wj, acc.y);
            acc.z = fmaf(f1.x, wj, acc.z);
            acc.w = fmaf(f1.y, wj, acc.w);
        }
    }
    *reinterpret_cast<float4*>(d_agg + (size_t)warp * 128 + lane * 4) = acc;
}

// ---------------- GRU --------------------------------------------------------
__global__ void k_gru() {
    int n = blockIdx.x;
    int f = threadIdx.x;
    const float* gi = d_gi + (size_t)n * 384;
    const float* gh = d_mgh + (size_t)n * 512 + 128;
    float r  = sigmoidf_(gi[f] + gh[f]);
    float z  = sigmoidf_(gi[128 + f] + gh[128 + f]);
    float nn = tanhf(gi[256 + f] + r * gh[256 + f]);
    float ho = d_h[(size_t)n * 128 + f];
    d_h[(size_t)n * 128 + f] = (1.0f - z) * nn + z * ho;
}

// ---------------- pooling + MLP ----------------------------------------------
__global__ void k_pool_init() {
    int i = blockIdx.x * blockDim.x + threadIdx.x;
    if (i < Gg * Hh) d_pooled[i] = -INFINITY;
}

__global__ void k_pool(const int* __restrict__ batch) {
    int i = blockIdx.x * blockDim.x + threadIdx.x;
    if (i >= Nn * Hh) return;
    int n = i >> 7, f = i & 127;
    float v = d_h[i];
    int g = batch[n];
    float* addr = &d_pooled[g * Hh + f];
    if (v >= 0.0f)
        atomicMax(reinterpret_cast<int*>(addr), __float_as_int(v));
    else
        atomicMin(reinterpret_cast<unsigned*>(addr), __float_as_uint(v));
}

__global__ void k_mlp1(const float* __restrict__ w, const float* __restrict__ b) {
    __shared__ float p[Hh];
    int g = blockIdx.x;
    p[threadIdx.x] = d_pooled[g * Hh + threadIdx.x];
    __syncthreads();
    for (int o = threadIdx.x; o < 4 * Hh; o += blockDim.x) {
        const float* wr = w + (size_t)o * Hh;
        float s = b[o];
        #pragma unroll 4
        for (int k = 0; k < Hh; k++) s = fmaf(p[k], wr[k], s);
        d_hid[g * 4 * Hh + o] = fmaxf(s, 0.0f);
    }
}

__global__ void k_mlp2(const float* __restrict__ w, const float* __restrict__ b,
                       float* __restrict__ out) {
    __shared__ float hsh[4 * Hh];
    int g = blockIdx.x;
    for (int i = threadIdx.x; i < 4 * Hh; i += blockDim.x)
        hsh[i] = d_hid[g * 4 * Hh + i];
    __syncthreads();
    int warp = threadIdx.x >> 5, lane = threadIdx.x & 31;
    if (warp < Cc) {
        const float* wr = w + (size_t)warp * (4 * Hh);
        float s = 0.0f;
        for (int k = lane; k < 4 * Hh; k += 32) s = fmaf(hsh[k], wr[k], s);
        #pragma unroll
        for (int off = 16; off; off >>= 1)
            s += __shfl_down_sync(0xffffffff, s, off);
        if (lane == 0) out[g * Cc + warp] = s + b[warp];
    }
}

// ---------------- launch ------------------------------------------------------
extern "C" void kernel_launch(void* const* d_in, const int* in_sizes, int n_in,
                              void* d_out, int out_size) {
    const float* x     = (const float*)d_in[0];
    const int*   ei    = (const int*)  d_in[1];
    const int*   batch = (const int*)  d_in[2];
    const float* ew    = (const float*)d_in[3];
    const float* weight= (const float*)d_in[4];
    const float* w_ih  = (const float*)d_in[5];
    const float* w_hh  = (const float*)d_in[6];
    const float* b_ih  = (const float*)d_in[7];
    const float* b_hh  = (const float*)d_in[8];
    const float* d1w   = (const float*)d_in[9];
    const float* d1b   = (const float*)d_in[10];
    const float* d2w   = (const float*)d_in[11];
    const float* d2b   = (const float*)d_in[12];
    float* out = (float*)d_out;

    float  *ph, *pmgh, *pagg, *pgi, *pbcat;
    __half *pwih16, *pBcat16;
    cudaGetSymbolAddress((void**)&ph,      d_h);
    cudaGetSymbolAddress((void**)&pmgh,    d_mgh);
    cudaGetSymbolAddress((void**)&pagg,    d_agg);
    cudaGetSymbolAddress((void**)&pgi,     d_gi);
    cudaGetSymbolAddress((void**)&pwih16,  d_wih16);
    cudaGetSymbolAddress((void**)&pBcat16, d_Bcat16);
    cudaGetSymbolAddress((void**)&pbcat,   d_bcat);

    const int GEMM_SMEM = 2 * 128 * HS * (int)sizeof(__half);   // 69.6 KB
    cudaFuncSetAttribute(k_gemm_h, cudaFuncAttributeMaxDynamicSharedMemorySize,
                         GEMM_SMEM);

    const int NH = Nn * Hh;
    // setup
    k_init_h<<<(NH + 255) / 256, 256>>>(x);
    k_prep_wih<<<(3 * Hh * Hh + 255) / 256, 256>>>(w_ih);
    k_build_bcat<<<(Ll * 512 * Hh + 255) / 256, 256>>>(weight, w_hh, b_hh);
    // CSR build
    k_deg_zero<<<(Nn + 255) / 256, 256>>>();
    k_hist<<<(Ee + 255) / 256, 256>>>(ei);
    k_scan<<<1, 1024>>>();
    k_scatter<<<(Ee + 255) / 256, 256>>>(ei, ew);

    const int MB = (Nn + 127) / 128;  // 391 row tiles
    for (int l = 0; l < Ll; l++) {
        // [m | gh] = h @ [W_l | w_hh^T]   (bias [0 | b_hh]) — exact R10 GEMM
        k_gemm_h<<<dim3(MB, 4), 256, GEMM_SMEM>>>(
            ph, pBcat16 + (size_t)l * 512 * Hh, pbcat, pmgh, Nn, 512);
        // compact fp16 copy of m for the gather
        k_m2h<<<(Nn * 64 + 255) / 256, 256>>>();
        // agg = CSR gather of m16[src]*w (fp32 accumulate)
        k_agg<<<(Nn * 32 + 255) / 256, 256>>>();
        // gi = agg @ w_ih^T + b_ih
        k_gemm_h<<<dim3(MB, 3), 256, GEMM_SMEM>>>(pagg, pwih16, b_ih, pgi, Nn, 384);
        // h = GRU(agg, h)
        k_gru<<<Nn, Hh>>>();
    }

    k_pool_init<<<(Gg * Hh + 255) / 256, 256>>>();
    k_pool<<<(NH + 255) / 256, 256>>>(batch);
    k_mlp1<<<Gg, Hh>>>(d1w, d1b);
    k_mlp2<<<Gg, 320>>>(d2w, d2b, out);
}

// round 17
// speedup vs baseline: 1.4336x; 1.0262x over previous
#include <cuda_runtime.h>
#include <cuda_fp16.h>
#include <math.h>

#define Nn 50000
#define Ee 1600000
#define INF_FEATS 64
#define Hh 128
#define Ll 5
#define Gg 512
#define Cc 10

#define HS 136   // half-stride per smem tile row: 128 + 8 pad -> word stride 68 ≡ 4 (mod 32)
#define WS 68    // word (uint32/half2) stride

// ---------------- scratch (device globals; no allocation allowed) ----------
__device__ float  d_h[Nn * Hh];            // node state
__device__ __half d_m16[Nn * Hh];          // m = h @ W_l  (fp16, gather source)
__device__ float  d_gh[Nn * 3 * Hh];       // h @ w_hh^T + b_hh (compact)
__device__ float  d_agg[Nn * Hh];          // gathered messages
__device__ float  d_gi[Nn * 3 * Hh];       // agg @ w_ih^T + b_ih
__device__ __half d_wih16[3 * Hh * Hh];    // w_ih [384][128] fp16 (n-major)
__device__ __half d_Bcat16[Ll * 512 * Hh]; // per-layer [c][k]: c<128 = W_l, c>=128 = w_hh^T
__device__ float  d_pooled[Gg * Hh];
__device__ float  d_hid[Gg * 4 * Hh];
// CSR scratch
__device__ int    d_deg[Nn];
__device__ int    d_rowstart[Nn + 1];
__device__ int    d_cursor[Nn];
__device__ int    d_esrc[Ee];
__device__ float  d_ews[Ee];

// ---------------- helpers ---------------------------------------------------
__device__ __forceinline__ float sigmoidf_(float x) {
    return 1.0f / (1.0f + expf(-x));
}

__device__ __forceinline__ void mma_f16(float c[4], const unsigned a[4],
                                        const unsigned b[2]) {
    asm volatile(
        "mma.sync.aligned.m16n8k16.row.col.f32.f16.f16.f32 "
        "{%0,%1,%2,%3}, {%4,%5,%6,%7}, {%8,%9}, {%0,%1,%2,%3};"
        : "+f"(c[0]), "+f"(c[1]), "+f"(c[2]), "+f"(c[3])
        : "r"(a[0]), "r"(a[1]), "r"(a[2]), "r"(a[3]), "r"(b[0]), "r"(b[1]));
}

// ---------------- setup kernels ---------------------------------------------

__global__ void k_init_h(const float* __restrict__ x) {
    int i = blockIdx.x * blockDim.x + threadIdx.x;
    if (i >= Nn * Hh) return;
    int n = i >> 7, f = i & 127;
    d_h[i] = (f < INF_FEATS) ? x[n * INF_FEATS + f] : 0.0f;
}

// wih16[n][k] = fp16(w_ih[n][k])  (identity layout copy-convert)
__global__ void k_prep_wih(const float* __restrict__ wih) {
    int i = blockIdx.x * blockDim.x + threadIdx.x;
    if (i < 3 * Hh * Hh) d_wih16[i] = __float2half_rn(wih[i]);
}

// Bcat16[l][c][k] = fp16( c<128 ? weight[l][k][c] : w_hh[c-128][k] )
__global__ void k_build_bcat(const float* __restrict__ weight,
                             const float* __restrict__ whh) {
    int i = blockIdx.x * blockDim.x + threadIdx.x;
    if (i >= Ll * 512 * Hh) return;
    int l = i / (512 * Hh);
    int r = i % (512 * Hh);
    int c = r / Hh, k = r % Hh;
    float v = (c < 128) ? weight[(size_t)l * Hh * Hh + k * Hh + c]
                        : whh[(size_t)(c - 128) * Hh + k];
    d_Bcat16[i] = __float2half_rn(v);
}

// ---------------- CSR build --------------------------------------------------
__global__ void k_deg_zero() {
    int i = blockIdx.x * blockDim.x + threadIdx.x;
    if (i < Nn) d_deg[i] = 0;
}

__global__ void k_hist(const int* __restrict__ ei) {
    int e = blockIdx.x * blockDim.x + threadIdx.x;
    if (e < Ee) atomicAdd(&d_deg[ei[Ee + e]], 1);
}

__global__ void k_scan() {
    __shared__ int sp[1024];
    const int CH = (Nn + 1023) / 1024;
    int t = threadIdx.x;
    int base = t * CH;
    int s = 0;
    for (int i = 0; i < CH; i++) {
        int idx = base + i;
        if (idx < Nn) s += d_deg[idx];
    }
    sp[t] = s;
    __syncthreads();
    for (int d = 1; d < 1024; d <<= 1) {
        int add = (t >= d) ? sp[t - d] : 0;
        __syncthreads();
        sp[t] += add;
        __syncthreads();
    }
    int off = sp[t] - s;
    for (int i = 0; i < CH; i++) {
        int idx = base + i;
        if (idx < Nn) {
            d_rowstart[idx] = off;
            d_cursor[idx] = off;
            off += d_deg[idx];
        }
    }
    if (t == 1023) d_rowstart[Nn] = off;
}

__global__ void k_scatter(const int* __restrict__ ei, const float* __restrict__ ew) {
    int e = blockIdx.x * blockDim.x + threadIdx.x;
    if (e >= Ee) return;
    int dst = ei[Ee + e];
    int pos = atomicAdd(&d_cursor[dst], 1);
    d_esrc[pos] = ei[e];
    d_ews[pos] = ew[e];
}

// ---------------- GEMM body macro (fp16 m16n8k16, 2 CTAs/SM) ------------------
// Shared by the fp32-out and fp16-out variants; only the epilogue differs.
#define GEMM_PROLOG_AND_MAINLOOP                                               \
    extern __shared__ __half smh[];                                            \
    __half* Ash = smh;                                                         \
    __half* Bsh = smh + 128 * HS;                                              \
    int m0 = blockIdx.x * 128;                                                 \
    int n0 = blockIdx.y * 128;                                                 \
    int tid = threadIdx.x;                                                     \
    _Pragma("unroll")                                                          \
    for (int i = 0; i < 16; i++) {                                             \
        int e = tid + i * 256;                                                 \
        int r = e >> 5, c4 = e & 31;                                           \
        float4 v = make_float4(0.f, 0.f, 0.f, 0.f);                            \
        if (m0 + r < M)                                                        \
            v = reinterpret_cast<const float4*>(A + (size_t)(m0 + r) * 128)[c4]; \
        __half2* dst = reinterpret_cast<__half2*>(Ash + r * HS + c4 * 4);      \
        dst[0] = __floats2half2_rn(v.x, v.y);                                  \
        dst[1] = __floats2half2_rn(v.z, v.w);                                  \
    }                                                                          \
    _Pragma("unroll")                                                          \
    for (int i = 0; i < 8; i++) {                                              \
        int e = tid + i * 256;                                                 \
        int r = e >> 4, c4 = e & 15;                                           \
        float4 v = reinterpret_cast<const float4*>(B16 + (size_t)(n0 + r) * 128)[c4]; \
        reinterpret_cast<float4*>(Bsh + r * HS)[c4] = v;                       \
    }                                                                          \
    __syncthreads();                                                           \
    int wid = tid >> 5, lane = tid & 31;                                       \
    int wm = (wid & 3) * 32;                                                   \
    int wn = (wid >> 2) * 64;                                                  \
    int lr = lane >> 2;                                                        \
    int lc = lane & 3;                                                         \
    float acc[2][8][4];                                                        \
    _Pragma("unroll")                                                          \
    for (int mt = 0; mt < 2; mt++)                                             \
        _Pragma("unroll")                                                      \
        for (int nt = 0; nt < 8; nt++)                                         \
            _Pragma("unroll")                                                  \
            for (int q = 0; q < 4; q++) acc[mt][nt][q] = 0.0f;                 \
    const unsigned* Asu = reinterpret_cast<const unsigned*>(Ash);              \
    const unsigned* Bsu = reinterpret_cast<const unsigned*>(Bsh);              \
    _Pragma("unroll")                                                          \
    for (int ks = 0; ks < 8; ks++) {                                           \
        int kh = ks * 8;                                                       \
        unsigned a[2][4], b[8][2];                                             \
        _Pragma("unroll")                                                      \
        for (int mt = 0; mt < 2; mt++) {                                       \
            const unsigned* ap = Asu + (wm + mt * 16 + lr) * WS + kh + lc;     \
            a[mt][0] = ap[0];                                                  \
            a[mt][1] = ap[8 * WS];                                             \
            a[mt][2] = ap[4];                                                  \
            a[mt][3] = ap[8 * WS + 4];                                         \
        }                                                                      \
        _Pragma("unroll")                                                      \
        for (int nt = 0; nt < 8; nt++) {                                       \
            const unsigned* bp = Bsu + (wn + nt * 8 + lr) * WS + kh + lc;      \
            b[nt][0] = bp[0];                                                  \
            b[nt][1] = bp[4];                                                  \
        }                                                                      \
        _Pragma("unroll")                                                      \
        for (int mt = 0; mt < 2; mt++)                                         \
            _Pragma("unroll")                                                  \
            for (int nt = 0; nt < 8; nt++)                                     \
                mma_f16(acc[mt][nt], a[mt], b[nt]);                            \
    }

// fp32 output (+bias): used for gh and gi
__global__ void __launch_bounds__(256, 2)
k_gemm_h(const float* __restrict__ A, const __half* __restrict__ B16,
         const float* __restrict__ bias, float* __restrict__ C,
         int M, int Nw) {
    GEMM_PROLOG_AND_MAINLOOP
    #pragma unroll
    for (int mt = 0; mt < 2; mt++) {
        #pragma unroll
        for (int nt = 0; nt < 8; nt++) {
            int row = m0 + wm + mt * 16 + lr;
            int col = n0 + wn + nt * 8 + lc * 2;
            float b0 = bias ? bias[col] : 0.0f;
            float b1 = bias ? bias[col + 1] : 0.0f;
            if (row < M) {
                float2 v = make_float2(acc[mt][nt][0] + b0, acc[mt][nt][1] + b1);
                *reinterpret_cast<float2*>(C + (size_t)row * Nw + col) = v;
            }
            if (row + 8 < M) {
                float2 v = make_float2(acc[mt][nt][2] + b0, acc[mt][nt][3] + b1);
                *reinterpret_cast<float2*>(C + (size_t)(row + 8) * Nw + col) = v;
            }
        }
    }
}

// fp16 output, no bias, Nw=128: used for m (direct gather-format store)
__global__ void __launch_bounds__(256, 2)
k_gemm_m16(const float* __restrict__ A, const __half* __restrict__ B16,
           __half* __restrict__ C, int M) {
    GEMM_PROLOG_AND_MAINLOOP
    #pragma unroll
    for (int mt = 0; mt < 2; mt++) {
        #pragma unroll
        for (int nt = 0; nt < 8; nt++) {
            int row = m0 + wm + mt * 16 + lr;
            int col = n0 + wn + nt * 8 + lc * 2;
            if (row < M)
                *reinterpret_cast<__half2*>(C + (size_t)row * 128 + col) =
                    __floats2half2_rn(acc[mt][nt][0], acc[mt][nt][1]);
            if (row + 8 < M)
                *reinterpret_cast<__half2*>(C + (size_t)(row + 8) * 128 + col) =
                    __floats2half2_rn(acc[mt][nt][2], acc[mt][nt][3]);
        }
    }
}

// ---------------- CSR aggregation: warp per node ------------------------------
// agg[n] = sum_e m16[src(e)] * w(e).  Lane owns 4 features (uint2 = 8 B).
__global__ void k_agg() {
    int warp = (blockIdx.x * blockDim.x + threadIdx.x) >> 5;
    if (warp >= Nn) return;
    int lane = threadIdx.x & 31;
    int beg = d_rowstart[warp];
    int end = d_rowstart[warp + 1];
    float4 acc = make_float4(0.f, 0.f, 0.f, 0.f);
    for (int base = beg; base < end; base += 32) {
        int idx = base + lane;
        int sid = 0;
        float w = 0.0f;
        if (idx < end) { sid = d_esrc[idx]; w = d_ews[idx]; }
        int cnt = min(32, end - base);
        #pragma unroll 4
        for (int j = 0; j < cnt; j++) {
            int s = __shfl_sync(0xffffffff, sid, j);
            float wj = __shfl_sync(0xffffffff, w, j);
            uint2 u = reinterpret_cast<const uint2*>(d_m16 + (size_t)s * 128)[lane];
            float2 f0 = __half22float2(*reinterpret_cast<__half2*>(&u.x));
            float2 f1 = __half22float2(*reinterpret_cast<__half2*>(&u.y));
            acc.x = fmaf(f0.x, wj, acc.x);
            acc.y = fmaf(f0.y, wj, acc.y);
            acc.z = fmaf(f1.x, wj, acc.z);
            acc.w = fmaf(f1.y, wj, acc.w);
        }
    }
    *reinterpret_cast<float4*>(d_agg + (size_t)warp * 128 + lane * 4) = acc;
}

// ---------------- GRU (2 nodes per 256-thread block) --------------------------
__global__ void k_gru() {
    int n = blockIdx.x * 2 + (threadIdx.x >> 7);
    int f = threadIdx.x & 127;
    if (n >= Nn) return;
    const float* gi = d_gi + (size_t)n * 384;
    const float* gh = d_gh + (size_t)n * 384;
    float r  = sigmoidf_(gi[f] + gh[f]);
    float z  = sigmoidf_(gi[128 + f] + gh[128 + f]);
    float nn = tanhf(gi[256 + f] + r * gh[256 + f]);
    float ho = d_h[(size_t)n * 128 + f];
    d_h[(size_t)n * 128 + f] = (1.0f - z) * nn + z * ho;
}

// ---------------- pooling + MLP ----------------------------------------------
__global__ void k_pool_init() {
    int i = blockIdx.x * blockDim.x + threadIdx.x;
    if (i < Gg * Hh) d_pooled[i] = -INFINITY;
}

__global__ void k_pool(const int* __restrict__ batch) {
    int i = blockIdx.x * blockDim.x + threadIdx.x;
    if (i >= Nn * Hh) return;
    int n = i >> 7, f = i & 127;
    float v = d_h[i];
    int g = batch[n];
    float* addr = &d_pooled[g * Hh + f];
    if (v >= 0.0f)
        atomicMax(reinterpret_cast<int*>(addr), __float_as_int(v));
    else
        atomicMin(reinterpret_cast<unsigned*>(addr), __float_as_uint(v));
}

__global__ void k_mlp1(const float* __restrict__ w, const float* __restrict__ b) {
    __shared__ float p[Hh];
    int g = blockIdx.x;
    p[threadIdx.x] = d_pooled[g * Hh + threadIdx.x];
    __syncthreads();
    for (int o = threadIdx.x; o < 4 * Hh; o += blockDim.x) {
        const float* wr = w + (size_t)o * Hh;
        float s = b[o];
        #pragma unroll 4
        for (int k = 0; k < Hh; k++) s = fmaf(p[k], wr[k], s);
        d_hid[g * 4 * Hh + o] = fmaxf(s, 0.0f);
    }
}

__global__ void k_mlp2(const float* __restrict__ w, const float* __restrict__ b,
                       float* __restrict__ out) {
    __shared__ float hsh[4 * Hh];
    int g = blockIdx.x;
    for (int i = threadIdx.x; i < 4 * Hh; i += blockDim.x)
        hsh[i] = d_hid[g * 4 * Hh + i];
    __syncthreads();
    int warp = threadIdx.x >> 5, lane = threadIdx.x & 31;
    if (warp < Cc) {
        const float* wr = w + (size_t)warp * (4 * Hh);
        float s = 0.0f;
        for (int k = lane; k < 4 * Hh; k += 32) s = fmaf(hsh[k], wr[k], s);
        #pragma unroll
        for (int off = 16; off; off >>= 1)
            s += __shfl_down_sync(0xffffffff, s, off);
        if (lane == 0) out[g * Cc + warp] = s + b[warp];
    }
}

// ---------------- launch ------------------------------------------------------
extern "C" void kernel_launch(void* const* d_in, const int* in_sizes, int n_in,
                              void* d_out, int out_size) {
    const float* x     = (const float*)d_in[0];
    const int*   ei    = (const int*)  d_in[1];
    const int*   batch = (const int*)  d_in[2];
    const float* ew    = (const float*)d_in[3];
    const float* weight= (const float*)d_in[4];
    const float* w_ih  = (const float*)d_in[5];
    const float* w_hh  = (const float*)d_in[6];
    const float* b_ih  = (const float*)d_in[7];
    const float* b_hh  = (const float*)d_in[8];
    const float* d1w   = (const float*)d_in[9];
    const float* d1b   = (const float*)d_in[10];
    const float* d2w   = (const float*)d_in[11];
    const float* d2b   = (const float*)d_in[12];
    float* out = (float*)d_out;

    float  *ph, *pgh, *pagg, *pgi;
    __half *pm16, *pwih16, *pBcat16;
    cudaGetSymbolAddress((void**)&ph,      d_h);
    cudaGetSymbolAddress((void**)&pm16,    d_m16);
    cudaGetSymbolAddress((void**)&pgh,     d_gh);
    cudaGetSymbolAddress((void**)&pagg,    d_agg);
    cudaGetSymbolAddress((void**)&pgi,     d_gi);
    cudaGetSymbolAddress((void**)&pwih16,  d_wih16);
    cudaGetSymbolAddress((void**)&pBcat16, d_Bcat16);

    const int GEMM_SMEM = 2 * 128 * HS * (int)sizeof(__half);   // 69.6 KB
    cudaFuncSetAttribute(k_gemm_h, cudaFuncAttributeMaxDynamicSharedMemorySize,
                         GEMM_SMEM);
    cudaFuncSetAttribute(k_gemm_m16, cudaFuncAttributeMaxDynamicSharedMemorySize,
                         GEMM_SMEM);

    const int NH = Nn * Hh;
    // setup
    k_init_h<<<(NH + 255) / 256, 256>>>(x);
    k_prep_wih<<<(3 * Hh * Hh + 255) / 256, 256>>>(w_ih);
    k_build_bcat<<<(Ll * 512 * Hh + 255) / 256, 256>>>(weight, w_hh);
    // CSR build
    k_deg_zero<<<(Nn + 255) / 256, 256>>>();
    k_hist<<<(Ee + 255) / 256, 256>>>(ei);
    k_scan<<<1, 1024>>>();
    k_scatter<<<(Ee + 255) / 256, 256>>>(ei, ew);

    const int MB = (Nn + 127) / 128;  // 391 row tiles
    for (int l = 0; l < Ll; l++) {
        const __half* Bl = pBcat16 + (size_t)l * 512 * Hh;
        // m16 = h @ W_l  (fp16 out, gather format)
        k_gemm_m16<<<dim3(MB, 1), 256, GEMM_SMEM>>>(ph, Bl, pm16, Nn);
        // gh = h @ w_hh^T + b_hh  (rows 128..511 of Bcat are w_hh^T n-major)
        k_gemm_h<<<dim3(MB, 3), 256, GEMM_SMEM>>>(
            ph, Bl + (size_t)128 * Hh, b_hh, pgh, Nn, 384);
        // agg = CSR gather of m16[src]*w (fp32 accumulate)
        k_agg<<<(Nn * 32 + 255) / 256, 256>>>();
        // gi = agg @ w_ih^T + b_ih
        k_gemm_h<<<dim3(MB, 3), 256, GEMM_SMEM>>>(pagg, pwih16, b_ih, pgi, Nn, 384);
        // h = GRU(agg, h)
        k_gru<<<(Nn + 1) / 2, 256>>>();
    }

    k_pool_init<<<(Gg * Hh + 255) / 256, 256>>>();
    k_pool<<<(NH + 255) / 256, 256>>>(batch);
    k_mlp1<<<Gg, Hh>>>(d1w, d1b);
    k_mlp2<<<Gg, 320>>>(d2w, d2b, out);
}